// round 15
// baseline (speedup 1.0000x reference)
#include <cuda_runtime.h>
#include <cuda_fp16.h>
#include <math.h>
#include <stdint.h>

#define SEQ 2048
#define DM  1024
#define NH  16
#define DK  64
#define DFF 4096
#define NL  4
#define LDQKV (3 * DM)

typedef __half h16;

// ---------------- device scratch (no cudaMalloc allowed) ----------------
__device__ h16 g_wqkvT[NL * 3 * DM * DM];     // [3*DM rows, DM cols] per layer
__device__ float g_bqkv[NL * 3 * DM];
__device__ h16 g_woT[NL * DM * DM];
__device__ h16 g_w1T[NL * DM * DFF];
__device__ h16 g_w2T[NL * DM * DFF];
__device__ h16 g_xh[SEQ * DM];
__device__ h16 g_qkv[SEQ * 3 * DM];           // fused q|k|v
__device__ h16 g_vth[DM * SEQ];               // V^T
__device__ h16 g_ch[SEQ * DM];
__device__ h16 g_hh[SEQ * DFF];
__device__ float g_tmp[SEQ * DM];

// ---------------- small helpers ----------------
__device__ __forceinline__ float tanh_fast(float y) {
    return 1.0f - 2.0f / (__expf(2.0f * y) + 1.0f);
}
__device__ __forceinline__ float gelu_f(float v) {
    return 0.5f * v * (1.0f + tanh_fast(0.7978845608028654f *
                                        (v + 0.044715f * v * v * v)));
}
__device__ __forceinline__ uint32_t pack2h(float x, float y) {
    __half2 p = __floats2half2_rn(x, y);
    return *(uint32_t*)&p;
}
__device__ __forceinline__ void cpa16(uint32_t dst, const void* src) {
    asm volatile("cp.async.cg.shared.global [%0], [%1], 16;" :: "r"(dst), "l"(src));
}
#define CP_COMMIT() asm volatile("cp.async.commit_group;" ::: "memory")
#define CP_WAIT0()  asm volatile("cp.async.wait_group 0;" ::: "memory")
#define CP_WAIT1()  asm volatile("cp.async.wait_group 1;" ::: "memory")
#define LDSM4(r, a) asm volatile( \
    "ldmatrix.sync.aligned.m8n8.x4.shared.b16 {%0,%1,%2,%3}, [%4];" \
    : "=r"((r)[0]), "=r"((r)[1]), "=r"((r)[2]), "=r"((r)[3]) : "r"(a))

__device__ __forceinline__ void mma16816(float* c, const uint32_t* a, const uint32_t* b) {
    asm volatile(
        "mma.sync.aligned.m16n8k16.row.col.f32.f16.f16.f32 "
        "{%0,%1,%2,%3}, {%4,%5,%6,%7}, {%8,%9}, {%0,%1,%2,%3};"
        : "+f"(c[0]), "+f"(c[1]), "+f"(c[2]), "+f"(c[3])
        : "r"(a[0]), "r"(a[1]), "r"(a[2]), "r"(a[3]), "r"(b[0]), "r"(b[1]));
}
__device__ __forceinline__ uint32_t sm_addr(const void* p) {
    return (uint32_t)__cvta_generic_to_shared(p);
}

// ---------------- mma.sync GEMM: MTx128 tile, pure fp16, 2 CTA/SM ----------------
// C = A @ B^T [+bias][gelu]; MT in {128, 64}
// EPI: 1 f32+bias, 3 fp16+bias, 4 gelu fp16+bias
template <int EPI, int MT>
__global__ __launch_bounds__(256, 2) void mmsync(
    const h16* __restrict__ Ah, const h16* __restrict__ Bh,
    const float* __restrict__ bias,
    float* __restrict__ Cf, h16* __restrict__ Ch,
    int K, int lda, int ldb, int ldc)
{
    constexpr int SP  = 40;
    constexpr int ASZ = MT * SP;           // A stage size (halfs)
    constexpr int BSZ = 128 * SP;          // B stage size
    constexpr int MF  = MT / 32;           // fragments per warp along M
    constexpr int NF  = 4;

    extern __shared__ h16 sm[];
    h16* sA = sm;                          // 2 * ASZ
    h16* sB = sA + 2 * ASZ;                // 2 * BSZ

    const int tid = threadIdx.x;
    const int wid = tid >> 5;
    const int lane = tid & 31;
    const int gid = lane >> 2, tig = lane & 3;
    const int bm = blockIdx.y * MT;
    const int bn = blockIdx.x * 128;

    const int wm0 = (wid >> 2) * (MT / 2); // 2 warp-rows
    const int wn0 = (wid & 3) * 32;        // 4 warp-cols

    float acc[MF][NF][4];
#pragma unroll
    for (int i = 0; i < MF; i++)
#pragma unroll
        for (int j = 0; j < NF; j++)
#pragma unroll
            for (int q = 0; q < 4; q++) acc[i][j][q] = 0.f;

    const int nk = K >> 5;

    auto loadStage = [&](int st, int k0) {
#pragma unroll
        for (int i = 0; i < MT / 64; i++) {   // A: MT*4 chunks of 8 halfs
            int ch = tid + i * 256;
            int row = ch >> 2, c = ch & 3;
            size_t ga = (size_t)(bm + row) * lda + k0 + c * 8;
            cpa16(sm_addr(&sA[st * ASZ + row * SP + c * 8]), Ah + ga);
        }
#pragma unroll
        for (int i = 0; i < 2; i++) {         // B: 512 chunks
            int ch = tid + i * 256;
            int row = ch >> 2, c = ch & 3;
            size_t gb = (size_t)(bn + row) * ldb + k0 + c * 8;
            cpa16(sm_addr(&sB[st * BSZ + row * SP + c * 8]), Bh + gb);
        }
    };

    loadStage(0, 0);
    CP_COMMIT();

    const int ar = lane & 15;
    const int acb = (lane >> 4) << 3;
    const int br = (lane < 16) ? (lane & 7) : 8 + (lane & 7);
    const int bcsel = ((lane >> 3) & 1) << 3;

    for (int kt = 0; kt < nk; kt++) {
        if (kt + 1 < nk) {
            loadStage((kt + 1) & 1, (kt + 1) << 5);
            CP_COMMIT();
            CP_WAIT1();
        } else {
            CP_WAIT0();
        }
        __syncthreads();

        const int st = kt & 1;
        const h16* aP = sA + st * ASZ;
        const h16* bP = sB + st * BSZ;

#pragma unroll
        for (int kk = 0; kk < 2; kk++) {
            const int koff = kk * 16;
            uint32_t af[MF][4];
#pragma unroll
            for (int mf = 0; mf < MF; mf++) {
                int r = wm0 + mf * 16 + ar;
                LDSM4(af[mf], sm_addr(&aP[r * SP + koff + acb]));
            }
            uint32_t bf[NF][2];
            const int bc = koff + bcsel;
#pragma unroll
            for (int nn = 0; nn < NF; nn += 2) {
                int r = wn0 + nn * 8 + br;
                uint32_t t[4];
                LDSM4(t, sm_addr(&bP[r * SP + bc]));
                bf[nn][0] = t[0]; bf[nn][1] = t[1];
                bf[nn + 1][0] = t[2]; bf[nn + 1][1] = t[3];
            }
#pragma unroll
            for (int mf = 0; mf < MF; mf++)
#pragma unroll
                for (int nf = 0; nf < NF; nf++)
                    mma16816(acc[mf][nf], af[mf], bf[nf]);
        }
        __syncthreads();
    }

    // ---------------- epilogue ----------------
#pragma unroll
    for (int mf = 0; mf < MF; mf++) {
        const int mA = bm + wm0 + mf * 16 + gid;
        const int mB = mA + 8;
#pragma unroll
        for (int nf = 0; nf < NF; nf++) {
            const int n = bn + wn0 + nf * 8 + 2 * tig;
            float b0 = bias[n], b1 = bias[n + 1];
            float v0 = acc[mf][nf][0] + b0, v1 = acc[mf][nf][1] + b1;
            float v2 = acc[mf][nf][2] + b0, v3 = acc[mf][nf][3] + b1;
            if (EPI == 1) {
                *(float2*)(Cf + (size_t)mA * ldc + n) = make_float2(v0, v1);
                *(float2*)(Cf + (size_t)mB * ldc + n) = make_float2(v2, v3);
            } else {
                if (EPI == 4) {
                    v0 = gelu_f(v0); v1 = gelu_f(v1);
                    v2 = gelu_f(v2); v3 = gelu_f(v3);
                }
                *(uint32_t*)(Ch + (size_t)mA * ldc + n) = pack2h(v0, v1);
                *(uint32_t*)(Ch + (size_t)mB * ldc + n) = pack2h(v2, v3);
            }
        }
    }
}

// ---------------- flash attention: S=QK^T/8, online softmax, O=PV ----------------
// grid (NH, SEQ/128), 256 threads. Q/K read from fused qkv (stride LDQKV).
__global__ __launch_bounds__(256) void flash_attn(
    const h16* __restrict__ qkv_g,      // q at +0, k at +DM, stride LDQKV
    const h16* __restrict__ vth_g,      // V^T [DM, SEQ]
    h16* __restrict__ ch_g)
{
    constexpr int KSP = 72, VSP = 136;
    constexpr int KST = 128 * KSP;
    constexpr int VST = 64 * VSP;
    const int h = blockIdx.x;
    const int q0 = blockIdx.y * 128;
    const int tid = threadIdx.x, wid = tid >> 5, lane = tid & 31;
    const int gid = lane >> 2, tig = lane & 3;

    const h16* qh_g = qkv_g;
    const h16* kh_g = qkv_g + DM;

    extern __shared__ h16 sm[];
    h16* sK = sm;                          // 2 * KST
    h16* sV = sK + 2 * KST;                // 2 * VST

    // ---- prologue: Q tile into stage-0 K buffer, extract frags ----
#pragma unroll
    for (int i = 0; i < 4; i++) {
        int ch = tid + i * 256;
        int row = ch >> 3, c = ch & 7;
        size_t g = (size_t)(q0 + row) * LDQKV + h * 64 + c * 8;
        cpa16(sm_addr(&sK[row * KSP + c * 8]), qh_g + g);
    }
    CP_COMMIT(); CP_WAIT0();
    __syncthreads();

    uint32_t qf[4][4];
    {
        const int ar = lane & 15, acb = (lane >> 4) << 3;
#pragma unroll
        for (int kf = 0; kf < 4; kf++) {
            int off = (wid * 16 + ar) * KSP + kf * 16 + acb;
            LDSM4(qf[kf], sm_addr(&sK[off]));
        }
    }
    __syncthreads();

    float oacc[8][4];
#pragma unroll
    for (int i = 0; i < 8; i++)
#pragma unroll
        for (int q = 0; q < 4; q++) oacc[i][q] = 0.f;
    float m0 = -1e30f, m1 = -1e30f, l0 = 0.f, l1 = 0.f;

    auto loadKV = [&](int st, int s0) {
        // K tile: 128 rows x 64 halfs = 1024 chunks of 8
#pragma unroll
        for (int i = 0; i < 4; i++) {
            int ch = tid + i * 256;
            int row = ch >> 3, c = ch & 7;
            size_t g = (size_t)(s0 + row) * LDQKV + h * 64 + c * 8;
            cpa16(sm_addr(&sK[st * KST + row * KSP + c * 8]), kh_g + g);
        }
        // V tile: 64 rows x 128 halfs = 1024 chunks of 8
#pragma unroll
        for (int i = 0; i < 4; i++) {
            int ch = tid + i * 256;
            int row = ch >> 4, c = ch & 15;
            size_t g = (size_t)(h * 64 + row) * SEQ + s0 + c * 8;
            cpa16(sm_addr(&sV[st * VST + row * VSP + c * 8]), vth_g + g);
        }
    };

    loadKV(0, 0);
    CP_COMMIT();

    const int br = (lane < 16) ? (lane & 7) : 8 + (lane & 7);
    const int bcsel = ((lane >> 3) & 1) << 3;

    for (int kt = 0; kt < SEQ / 128; kt++) {
        if (kt + 1 < SEQ / 128) {
            loadKV((kt + 1) & 1, (kt + 1) * 128);
            CP_COMMIT();
            CP_WAIT1();
        } else {
            CP_WAIT0();
        }
        __syncthreads();

        const int st = kt & 1;
        const h16* kP = sK + st * KST;
        const h16* vP = sV + st * VST;

        float sacc[16][4];
#pragma unroll
        for (int i = 0; i < 16; i++)
#pragma unroll
            for (int q = 0; q < 4; q++) sacc[i][q] = 0.f;

#pragma unroll
        for (int kf = 0; kf < 4; kf++) {
            const int bc = kf * 16 + bcsel;
#pragma unroll
            for (int nn = 0; nn < 16; nn += 2) {
                uint32_t t[4];
                LDSM4(t, sm_addr(&kP[(nn * 8 + br) * KSP + bc]));
                mma16816(sacc[nn], qf[kf], t);
                mma16816(sacc[nn + 1], qf[kf], t + 2);
            }
        }

        float tm0 = -1e30f, tm1 = -1e30f;
#pragma unroll
        for (int nf = 0; nf < 16; nf++) {
            sacc[nf][0] *= 0.125f; sacc[nf][1] *= 0.125f;
            sacc[nf][2] *= 0.125f; sacc[nf][3] *= 0.125f;
            tm0 = fmaxf(tm0, fmaxf(sacc[nf][0], sacc[nf][1]));
            tm1 = fmaxf(tm1, fmaxf(sacc[nf][2], sacc[nf][3]));
        }
        tm0 = fmaxf(tm0, __shfl_xor_sync(0xffffffffu, tm0, 1));
        tm0 = fmaxf(tm0, __shfl_xor_sync(0xffffffffu, tm0, 2));
        tm1 = fmaxf(tm1, __shfl_xor_sync(0xffffffffu, tm1, 1));
        tm1 = fmaxf(tm1, __shfl_xor_sync(0xffffffffu, tm1, 2));

        const float mn0 = fmaxf(m0, tm0), mn1 = fmaxf(m1, tm1);
        const float a0 = __expf(m0 - mn0), a1 = __expf(m1 - mn1);

        float rs0 = 0.f, rs1 = 0.f;
#pragma unroll
        for (int nf = 0; nf < 16; nf++) {
            sacc[nf][0] = __expf(sacc[nf][0] - mn0);
            sacc[nf][1] = __expf(sacc[nf][1] - mn0);
            sacc[nf][2] = __expf(sacc[nf][2] - mn1);
            sacc[nf][3] = __expf(sacc[nf][3] - mn1);
            rs0 += sacc[nf][0] + sacc[nf][1];
            rs1 += sacc[nf][2] + sacc[nf][3];
        }
        rs0 += __shfl_xor_sync(0xffffffffu, rs0, 1);
        rs0 += __shfl_xor_sync(0xffffffffu, rs0, 2);
        rs1 += __shfl_xor_sync(0xffffffffu, rs1, 1);
        rs1 += __shfl_xor_sync(0xffffffffu, rs1, 2);

        m0 = mn0; m1 = mn1;
        l0 = l0 * a0 + rs0;
        l1 = l1 * a1 + rs1;

#pragma unroll
        for (int nf = 0; nf < 8; nf++) {
            oacc[nf][0] *= a0; oacc[nf][1] *= a0;
            oacc[nf][2] *= a1; oacc[nf][3] *= a1;
        }

#pragma unroll
        for (int j = 0; j < 8; j++) {
            uint32_t pa[4];
            pa[0] = pack2h(sacc[2 * j][0], sacc[2 * j][1]);
            pa[1] = pack2h(sacc[2 * j][2], sacc[2 * j][3]);
            pa[2] = pack2h(sacc[2 * j + 1][0], sacc[2 * j + 1][1]);
            pa[3] = pack2h(sacc[2 * j + 1][2], sacc[2 * j + 1][3]);
            const int bc = j * 16 + bcsel;
#pragma unroll
            for (int nn = 0; nn < 8; nn += 2) {
                uint32_t t[4];
                LDSM4(t, sm_addr(&vP[(nn * 8 + br) * VSP + bc]));
                mma16816(oacc[nn], pa, t);
                mma16816(oacc[nn + 1], pa, t + 2);
            }
        }
        __syncthreads();
    }

    // ---- epilogue: O/l, store ctx fp16 ----
    const float il0 = 1.f / l0, il1 = 1.f / l1;
    const int mA = q0 + wid * 16 + gid;
    const int mB = mA + 8;
#pragma unroll
    for (int nf = 0; nf < 8; nf++) {
        const int col = h * 64 + nf * 8 + 2 * tig;
        *(uint32_t*)(ch_g + (size_t)mA * DM + col) =
            pack2h(oacc[nf][0] * il0, oacc[nf][1] * il0);
        *(uint32_t*)(ch_g + (size_t)mB * DM + col) =
            pack2h(oacc[nf][2] * il1, oacc[nf][3] * il1);
    }
}

// ---------------- transpose + convert weights: W[R,C] fp32 -> WT[C,R] fp16 ----------------
__global__ void trans_cvt_k(const float* __restrict__ in, h16* __restrict__ oh,
                            int R, int C, long long izs, long long ozs)
{
    __shared__ float t[32][33];
    in += (size_t)blockIdx.z * izs;
    oh += (size_t)blockIdx.z * ozs;
    const int r0 = blockIdx.y * 32, c0 = blockIdx.x * 32;
    const int tx = threadIdx.x, ty = threadIdx.y;
#pragma unroll
    for (int i = 0; i < 32; i += 8)
        t[ty + i][tx] = in[(size_t)(r0 + ty + i) * C + c0 + tx];
    __syncthreads();
#pragma unroll
    for (int i = 0; i < 32; i += 8)
        oh[(size_t)(c0 + ty + i) * R + r0 + tx] = __float2half_rn(t[tx][ty + i]);
}

// ---------------- bias concat: [bq|bk|bv] per layer ----------------
__global__ void concat_bias_k(const float* __restrict__ bq, const float* __restrict__ bk,
                              const float* __restrict__ bv, float* __restrict__ out)
{
    int l = blockIdx.x, w = blockIdx.y, i = threadIdx.x;
    const float* s = (w == 0) ? bq : ((w == 1) ? bk : bv);
    out[(size_t)(l * 3 + w) * DM + i] = s[(size_t)l * DM + i];
}

// ---------------- strided fp16 transpose: a[R,C] (lda) -> at[C,R] (ldat) ----------------
__global__ void trans_h_k(const h16* __restrict__ a, h16* __restrict__ at,
                          int lda, int ldat)
{
    __shared__ h16 ta[32][33];
    const int r0 = blockIdx.y * 32, c0 = blockIdx.x * 32;
    const int tx = threadIdx.x, ty = threadIdx.y;
#pragma unroll
    for (int i = 0; i < 32; i += 8)
        ta[ty + i][tx] = a[(size_t)(r0 + ty + i) * lda + c0 + tx];
    __syncthreads();
#pragma unroll
    for (int i = 0; i < 32; i += 8)
        at[(size_t)(c0 + ty + i) * ldat + r0 + tx] = ta[tx][ty + i];
}

// ---------------- elementwise fp32 -> fp16 ----------------
__global__ void cvt_h_k(const float* __restrict__ x, h16* __restrict__ h, int n)
{
    int i = blockIdx.x * 256 + threadIdx.x;
    if (i < n) h[i] = __float2half_rn(x[i]);
}

// ---------------- residual + LayerNorm, writes x fp32 and fp16 ----------------
__global__ __launch_bounds__(256) void add_ln_k(
    float* __restrict__ x, const float* __restrict__ y,
    const float* __restrict__ g, const float* __restrict__ b,
    h16* __restrict__ xh)
{
    __shared__ float r[DM];
    __shared__ float red[256];
    const int tid = threadIdx.x;
    const size_t off = (size_t)blockIdx.x * DM;

    float lsum = 0.f;
    for (int j = tid; j < DM; j += 256) {
        float v = x[off + j] + y[off + j];
        r[j] = v;
        lsum += v;
    }
    red[tid] = lsum; __syncthreads();
    for (int st = 128; st > 0; st >>= 1) {
        if (tid < st) red[tid] += red[tid + st];
        __syncthreads();
    }
    const float mu = red[0] * (1.0f / DM);
    __syncthreads();

    float lv = 0.f;
    for (int j = tid; j < DM; j += 256) {
        float d = r[j] - mu;
        lv += d * d;
    }
    red[tid] = lv; __syncthreads();
    for (int st = 128; st > 0; st >>= 1) {
        if (tid < st) red[tid] += red[tid + st];
        __syncthreads();
    }
    const float rstd = rsqrtf(red[0] * (1.0f / DM) + 1e-5f);

    for (int j = tid; j < DM; j += 256) {
        float v = (r[j] - mu) * rstd * g[j] + b[j];
        x[off + j] = v;
        xh[off + j] = __float2half_rn(v);
    }
}

// ---------------- host launch ----------------
static const int SMEM128 = (2 * 128 * 40 + 2 * 128 * 40) * 2;    // 40960
static const int SMEM64  = (2 * 64 * 40 + 2 * 128 * 40) * 2;     // 30720
static const int SMEMFA  = (2 * 128 * 72 + 2 * 64 * 136) * 2;    // 71680

extern "C" void kernel_launch(void* const* d_in, const int* in_sizes, int n_in,
                              void* d_out, int out_size)
{
    const float* x_in = (const float*)d_in[0];
    const float* wq = (const float*)d_in[1];
    const float* bq = (const float*)d_in[2];
    const float* wk = (const float*)d_in[3];
    const float* bk = (const float*)d_in[4];
    const float* wv = (const float*)d_in[5];
    const float* bv = (const float*)d_in[6];
    const float* wo = (const float*)d_in[7];
    const float* bo = (const float*)d_in[8];
    const float* w1 = (const float*)d_in[9];
    const float* b1 = (const float*)d_in[10];
    const float* w2 = (const float*)d_in[11];
    const float* b2 = (const float*)d_in[12];
    const float* ln1g = (const float*)d_in[13];
    const float* ln1b = (const float*)d_in[14];
    const float* ln2g = (const float*)d_in[15];
    const float* ln2b = (const float*)d_in[16];

    float* x = (float*)d_out;

    h16 *wqkvT, *woT, *w1T, *w2T;
    h16 *xh, *qkv, *vth, *ch, *hh;
    float *tmp, *bqkv;
    cudaGetSymbolAddress((void**)&wqkvT, g_wqkvT);
    cudaGetSymbolAddress((void**)&bqkv, g_bqkv);
    cudaGetSymbolAddress((void**)&woT, g_woT);
    cudaGetSymbolAddress((void**)&w1T, g_w1T);
    cudaGetSymbolAddress((void**)&w2T, g_w2T);
    cudaGetSymbolAddress((void**)&xh, g_xh);
    cudaGetSymbolAddress((void**)&qkv, g_qkv);
    cudaGetSymbolAddress((void**)&vth, g_vth);
    cudaGetSymbolAddress((void**)&ch, g_ch);
    cudaGetSymbolAddress((void**)&hh, g_hh);
    cudaGetSymbolAddress((void**)&tmp, g_tmp);

    cudaFuncSetAttribute(mmsync<3, 64>,  cudaFuncAttributeMaxDynamicSharedMemorySize, SMEM64);
    cudaFuncSetAttribute(mmsync<1, 64>,  cudaFuncAttributeMaxDynamicSharedMemorySize, SMEM64);
    cudaFuncSetAttribute(mmsync<4, 128>, cudaFuncAttributeMaxDynamicSharedMemorySize, SMEM128);
    cudaFuncSetAttribute(flash_attn, cudaFuncAttributeMaxDynamicSharedMemorySize, SMEMFA);

    const dim3 tb(32, 8);
    const long long WZ = (long long)DM * DM;
    const long long QZ = 3LL * DM * DM;
    trans_cvt_k<<<dim3(DM / 32, DM / 32, NL), tb>>>(wq, wqkvT, DM, DM, WZ, QZ);
    trans_cvt_k<<<dim3(DM / 32, DM / 32, NL), tb>>>(wk, wqkvT + (size_t)DM * DM, DM, DM, WZ, QZ);
    trans_cvt_k<<<dim3(DM / 32, DM / 32, NL), tb>>>(wv, wqkvT + 2 * (size_t)DM * DM, DM, DM, WZ, QZ);
    trans_cvt_k<<<dim3(DM / 32, DM / 32, NL), tb>>>(wo, woT, DM, DM, WZ, WZ);
    trans_cvt_k<<<dim3(DFF / 32, DM / 32, NL), tb>>>(w1, w1T, DM, DFF,
        (long long)DM * DFF, (long long)DM * DFF);
    trans_cvt_k<<<dim3(DM / 32, DFF / 32, NL), tb>>>(w2, w2T, DFF, DM,
        (long long)DM * DFF, (long long)DM * DFF);
    concat_bias_k<<<dim3(NL, 3), DM>>>(bq, bk, bv, bqkv);

    cudaMemcpyAsync(x, x_in, (size_t)SEQ * DM * sizeof(float), cudaMemcpyDeviceToDevice);
    cvt_h_k<<<(SEQ * DM) / 256, 256>>>(x_in, xh, SEQ * DM);

    const dim3 gQKV(3 * DM / 128, SEQ / 64);   // (24,32) = 768 CTAs
    const dim3 gP(DM / 128, SEQ / 64);         // (8,32)  = 256 CTAs
    const dim3 gFA(NH, SEQ / 128);             // (16,16)
    const dim3 gF1(DFF / 128, SEQ / 128);      // (32,16) = 512 CTAs

    for (int l = 0; l < NL; l++) {
        const size_t lW = (size_t)l * DM * DM;
        const size_t lQ = (size_t)l * 3 * DM * DM;
        const size_t lF = (size_t)l * DM * DFF;

        // fused q|k|v projection (MT=64)
        mmsync<3, 64><<<gQKV, 256, SMEM64>>>(xh, wqkvT + lQ, bqkv + (size_t)l * 3 * DM,
            nullptr, qkv, DM, DM, DM, LDQKV);
        // V^T from qkv's v slice (stride LDQKV)
        trans_h_k<<<dim3(DM / 32, SEQ / 32), tb>>>(qkv + 2 * DM, vth, LDQKV, SEQ);

        // fused attention: scores + softmax + AV
        flash_attn<<<gFA, 256, SMEMFA>>>(qkv, vth, ch);

        // attn_out = ctx @ Wo + bo (MT=64)
        mmsync<1, 64><<<gP, 256, SMEM64>>>(ch, woT + lW, bo + l * DM,
            tmp, nullptr, DM, DM, DM, DM);

        add_ln_k<<<SEQ, 256>>>(x, tmp, ln1g + l * DM, ln1b + l * DM, xh);

        // h = gelu(x @ W1 + b1) (MT=128)
        mmsync<4, 128><<<gF1, 256, SMEM128>>>(xh, w1T + lF, b1 + l * DFF,
            nullptr, hh, DM, DM, DM, DFF);

        // ffn_out = h @ W2 + b2 (MT=64)
        mmsync<1, 64><<<gP, 256, SMEM64>>>(hh, w2T + lF, b2 + l * DM,
            tmp, nullptr, DFF, DFF, DFF, DM);

        add_ln_k<<<SEQ, 256>>>(x, tmp, ln2g + l * DM, ln2b + l * DM, xh);
    }
}

// round 16
// speedup vs baseline: 1.0412x; 1.0412x over previous
#include <cuda_runtime.h>
#include <cuda_fp16.h>
#include <math.h>
#include <stdint.h>

#define SEQ 2048
#define DM  1024
#define NH  16
#define DK  64
#define DFF 4096
#define NL  4
#define LDQKV (3 * DM)

typedef __half h16;

// ---------------- device scratch (no cudaMalloc allowed) ----------------
__device__ h16 g_wqkvT[NL * 3 * DM * DM];     // [3*DM rows, DM cols] per layer
__device__ float g_bqkv[NL * 3 * DM];
__device__ h16 g_woT[NL * DM * DM];
__device__ h16 g_w1T[NL * DM * DFF];
__device__ h16 g_w2T[NL * DM * DFF];
__device__ h16 g_xh[SEQ * DM];
__device__ h16 g_qkv[SEQ * 3 * DM];           // fused q|k|v
__device__ h16 g_vth[DM * SEQ];               // V^T
__device__ h16 g_ch[SEQ * DM];
__device__ h16 g_hh[SEQ * DFF];
__device__ float g_tmp[SEQ * DM];

// ---------------- small helpers ----------------
__device__ __forceinline__ float tanh_fast(float y) {
    return 1.0f - 2.0f / (__expf(2.0f * y) + 1.0f);
}
__device__ __forceinline__ float gelu_f(float v) {
    return 0.5f * v * (1.0f + tanh_fast(0.7978845608028654f *
                                        (v + 0.044715f * v * v * v)));
}
__device__ __forceinline__ uint32_t pack2h(float x, float y) {
    __half2 p = __floats2half2_rn(x, y);
    return *(uint32_t*)&p;
}
__device__ __forceinline__ void cpa16(uint32_t dst, const void* src) {
    asm volatile("cp.async.cg.shared.global [%0], [%1], 16;" :: "r"(dst), "l"(src));
}
#define CP_COMMIT() asm volatile("cp.async.commit_group;" ::: "memory")
#define CP_WAIT0()  asm volatile("cp.async.wait_group 0;" ::: "memory")
#define CP_WAIT1()  asm volatile("cp.async.wait_group 1;" ::: "memory")
#define LDSM4(r, a) asm volatile( \
    "ldmatrix.sync.aligned.m8n8.x4.shared.b16 {%0,%1,%2,%3}, [%4];" \
    : "=r"((r)[0]), "=r"((r)[1]), "=r"((r)[2]), "=r"((r)[3]) : "r"(a))

__device__ __forceinline__ void mma16816(float* c, const uint32_t* a, const uint32_t* b) {
    asm volatile(
        "mma.sync.aligned.m16n8k16.row.col.f32.f16.f16.f32 "
        "{%0,%1,%2,%3}, {%4,%5,%6,%7}, {%8,%9}, {%0,%1,%2,%3};"
        : "+f"(c[0]), "+f"(c[1]), "+f"(c[2]), "+f"(c[3])
        : "r"(a[0]), "r"(a[1]), "r"(a[2]), "r"(a[3]), "r"(b[0]), "r"(b[1]));
}
__device__ __forceinline__ uint32_t sm_addr(const void* p) {
    return (uint32_t)__cvta_generic_to_shared(p);
}

// ---------------- mma.sync GEMM: MTx128 tile, pure fp16, 2 CTA/SM ----------------
// C = A @ B^T [+bias][gelu]; MT in {128, 64}
// EPI: 1 f32+bias, 3 fp16+bias, 4 gelu fp16+bias
template <int EPI, int MT>
__global__ __launch_bounds__(256, 2) void mmsync(
    const h16* __restrict__ Ah, const h16* __restrict__ Bh,
    const float* __restrict__ bias,
    float* __restrict__ Cf, h16* __restrict__ Ch,
    int K, int lda, int ldb, int ldc)
{
    constexpr int SP  = 40;
    constexpr int ASZ = MT * SP;           // A stage size (halfs)
    constexpr int BSZ = 128 * SP;          // B stage size
    constexpr int MF  = MT / 32;           // fragments per warp along M
    constexpr int NF  = 4;

    extern __shared__ h16 sm[];
    h16* sA = sm;                          // 2 * ASZ
    h16* sB = sA + 2 * ASZ;                // 2 * BSZ

    const int tid = threadIdx.x;
    const int wid = tid >> 5;
    const int lane = tid & 31;
    const int gid = lane >> 2, tig = lane & 3;
    const int bm = blockIdx.y * MT;
    const int bn = blockIdx.x * 128;

    const int wm0 = (wid >> 2) * (MT / 2); // 2 warp-rows
    const int wn0 = (wid & 3) * 32;        // 4 warp-cols

    float acc[MF][NF][4];
#pragma unroll
    for (int i = 0; i < MF; i++)
#pragma unroll
        for (int j = 0; j < NF; j++)
#pragma unroll
            for (int q = 0; q < 4; q++) acc[i][j][q] = 0.f;

    const int nk = K >> 5;

    auto loadStage = [&](int st, int k0) {
#pragma unroll
        for (int i = 0; i < MT / 64; i++) {   // A: MT*4 chunks of 8 halfs
            int ch = tid + i * 256;
            int row = ch >> 2, c = ch & 3;
            size_t ga = (size_t)(bm + row) * lda + k0 + c * 8;
            cpa16(sm_addr(&sA[st * ASZ + row * SP + c * 8]), Ah + ga);
        }
#pragma unroll
        for (int i = 0; i < 2; i++) {         // B: 512 chunks
            int ch = tid + i * 256;
            int row = ch >> 2, c = ch & 3;
            size_t gb = (size_t)(bn + row) * ldb + k0 + c * 8;
            cpa16(sm_addr(&sB[st * BSZ + row * SP + c * 8]), Bh + gb);
        }
    };

    loadStage(0, 0);
    CP_COMMIT();

    const int ar = lane & 15;
    const int acb = (lane >> 4) << 3;
    const int br = (lane < 16) ? (lane & 7) : 8 + (lane & 7);
    const int bcsel = ((lane >> 3) & 1) << 3;

    for (int kt = 0; kt < nk; kt++) {
        if (kt + 1 < nk) {
            loadStage((kt + 1) & 1, (kt + 1) << 5);
            CP_COMMIT();
            CP_WAIT1();
        } else {
            CP_WAIT0();
        }
        __syncthreads();

        const int st = kt & 1;
        const h16* aP = sA + st * ASZ;
        const h16* bP = sB + st * BSZ;

#pragma unroll
        for (int kk = 0; kk < 2; kk++) {
            const int koff = kk * 16;
            uint32_t af[MF][4];
#pragma unroll
            for (int mf = 0; mf < MF; mf++) {
                int r = wm0 + mf * 16 + ar;
                LDSM4(af[mf], sm_addr(&aP[r * SP + koff + acb]));
            }
            uint32_t bf[NF][2];
            const int bc = koff + bcsel;
#pragma unroll
            for (int nn = 0; nn < NF; nn += 2) {
                int r = wn0 + nn * 8 + br;
                uint32_t t[4];
                LDSM4(t, sm_addr(&bP[r * SP + bc]));
                bf[nn][0] = t[0]; bf[nn][1] = t[1];
                bf[nn + 1][0] = t[2]; bf[nn + 1][1] = t[3];
            }
#pragma unroll
            for (int mf = 0; mf < MF; mf++)
#pragma unroll
                for (int nf = 0; nf < NF; nf++)
                    mma16816(acc[mf][nf], af[mf], bf[nf]);
        }
        __syncthreads();
    }

    // ---------------- epilogue ----------------
#pragma unroll
    for (int mf = 0; mf < MF; mf++) {
        const int mA = bm + wm0 + mf * 16 + gid;
        const int mB = mA + 8;
#pragma unroll
        for (int nf = 0; nf < NF; nf++) {
            const int n = bn + wn0 + nf * 8 + 2 * tig;
            float b0 = bias[n], b1 = bias[n + 1];
            float v0 = acc[mf][nf][0] + b0, v1 = acc[mf][nf][1] + b1;
            float v2 = acc[mf][nf][2] + b0, v3 = acc[mf][nf][3] + b1;
            if (EPI == 1) {
                *(float2*)(Cf + (size_t)mA * ldc + n) = make_float2(v0, v1);
                *(float2*)(Cf + (size_t)mB * ldc + n) = make_float2(v2, v3);
            } else {
                if (EPI == 4) {
                    v0 = gelu_f(v0); v1 = gelu_f(v1);
                    v2 = gelu_f(v2); v3 = gelu_f(v3);
                }
                *(uint32_t*)(Ch + (size_t)mA * ldc + n) = pack2h(v0, v1);
                *(uint32_t*)(Ch + (size_t)mB * ldc + n) = pack2h(v2, v3);
            }
        }
    }
}

// ---------------- flash attention: S=QK^T/8, online softmax, O=PV ----------------
// grid (NH, SEQ/128), 256 threads. Q/K read from fused qkv (stride LDQKV).
__global__ __launch_bounds__(256) void flash_attn(
    const h16* __restrict__ qkv_g,      // q at +0, k at +DM, stride LDQKV
    const h16* __restrict__ vth_g,      // V^T [DM, SEQ]
    h16* __restrict__ ch_g)
{
    constexpr int KSP = 72, VSP = 136;
    constexpr int KST = 128 * KSP;
    constexpr int VST = 64 * VSP;
    const int h = blockIdx.x;
    const int q0 = blockIdx.y * 128;
    const int tid = threadIdx.x, wid = tid >> 5, lane = tid & 31;
    const int gid = lane >> 2, tig = lane & 3;

    const h16* qh_g = qkv_g;
    const h16* kh_g = qkv_g + DM;

    extern __shared__ h16 sm[];
    h16* sK = sm;                          // 2 * KST
    h16* sV = sK + 2 * KST;                // 2 * VST

    // ---- prologue: Q tile into stage-0 K buffer, extract frags ----
#pragma unroll
    for (int i = 0; i < 4; i++) {
        int ch = tid + i * 256;
        int row = ch >> 3, c = ch & 7;
        size_t g = (size_t)(q0 + row) * LDQKV + h * 64 + c * 8;
        cpa16(sm_addr(&sK[row * KSP + c * 8]), qh_g + g);
    }
    CP_COMMIT(); CP_WAIT0();
    __syncthreads();

    uint32_t qf[4][4];
    {
        const int ar = lane & 15, acb = (lane >> 4) << 3;
#pragma unroll
        for (int kf = 0; kf < 4; kf++) {
            int off = (wid * 16 + ar) * KSP + kf * 16 + acb;
            LDSM4(qf[kf], sm_addr(&sK[off]));
        }
    }
    __syncthreads();

    float oacc[8][4];
#pragma unroll
    for (int i = 0; i < 8; i++)
#pragma unroll
        for (int q = 0; q < 4; q++) oacc[i][q] = 0.f;
    float m0 = -1e30f, m1 = -1e30f, l0 = 0.f, l1 = 0.f;

    auto loadKV = [&](int st, int s0) {
        // K tile: 128 rows x 64 halfs = 1024 chunks of 8
#pragma unroll
        for (int i = 0; i < 4; i++) {
            int ch = tid + i * 256;
            int row = ch >> 3, c = ch & 7;
            size_t g = (size_t)(s0 + row) * LDQKV + h * 64 + c * 8;
            cpa16(sm_addr(&sK[st * KST + row * KSP + c * 8]), kh_g + g);
        }
        // V tile: 64 rows x 128 halfs = 1024 chunks of 8
#pragma unroll
        for (int i = 0; i < 4; i++) {
            int ch = tid + i * 256;
            int row = ch >> 4, c = ch & 15;
            size_t g = (size_t)(h * 64 + row) * SEQ + s0 + c * 8;
            cpa16(sm_addr(&sV[st * VST + row * VSP + c * 8]), vth_g + g);
        }
    };

    loadKV(0, 0);
    CP_COMMIT();

    const int br = (lane < 16) ? (lane & 7) : 8 + (lane & 7);
    const int bcsel = ((lane >> 3) & 1) << 3;

    for (int kt = 0; kt < SEQ / 128; kt++) {
        if (kt + 1 < SEQ / 128) {
            loadKV((kt + 1) & 1, (kt + 1) * 128);
            CP_COMMIT();
            CP_WAIT1();
        } else {
            CP_WAIT0();
        }
        __syncthreads();

        const int st = kt & 1;
        const h16* kP = sK + st * KST;
        const h16* vP = sV + st * VST;

        float sacc[16][4];
#pragma unroll
        for (int i = 0; i < 16; i++)
#pragma unroll
            for (int q = 0; q < 4; q++) sacc[i][q] = 0.f;

#pragma unroll
        for (int kf = 0; kf < 4; kf++) {
            const int bc = kf * 16 + bcsel;
#pragma unroll
            for (int nn = 0; nn < 16; nn += 2) {
                uint32_t t[4];
                LDSM4(t, sm_addr(&kP[(nn * 8 + br) * KSP + bc]));
                mma16816(sacc[nn], qf[kf], t);
                mma16816(sacc[nn + 1], qf[kf], t + 2);
            }
        }

        float tm0 = -1e30f, tm1 = -1e30f;
#pragma unroll
        for (int nf = 0; nf < 16; nf++) {
            sacc[nf][0] *= 0.125f; sacc[nf][1] *= 0.125f;
            sacc[nf][2] *= 0.125f; sacc[nf][3] *= 0.125f;
            tm0 = fmaxf(tm0, fmaxf(sacc[nf][0], sacc[nf][1]));
            tm1 = fmaxf(tm1, fmaxf(sacc[nf][2], sacc[nf][3]));
        }
        tm0 = fmaxf(tm0, __shfl_xor_sync(0xffffffffu, tm0, 1));
        tm0 = fmaxf(tm0, __shfl_xor_sync(0xffffffffu, tm0, 2));
        tm1 = fmaxf(tm1, __shfl_xor_sync(0xffffffffu, tm1, 1));
        tm1 = fmaxf(tm1, __shfl_xor_sync(0xffffffffu, tm1, 2));

        const float mn0 = fmaxf(m0, tm0), mn1 = fmaxf(m1, tm1);
        const float a0 = __expf(m0 - mn0), a1 = __expf(m1 - mn1);

        float rs0 = 0.f, rs1 = 0.f;
#pragma unroll
        for (int nf = 0; nf < 16; nf++) {
            sacc[nf][0] = __expf(sacc[nf][0] - mn0);
            sacc[nf][1] = __expf(sacc[nf][1] - mn0);
            sacc[nf][2] = __expf(sacc[nf][2] - mn1);
            sacc[nf][3] = __expf(sacc[nf][3] - mn1);
            rs0 += sacc[nf][0] + sacc[nf][1];
            rs1 += sacc[nf][2] + sacc[nf][3];
        }
        rs0 += __shfl_xor_sync(0xffffffffu, rs0, 1);
        rs0 += __shfl_xor_sync(0xffffffffu, rs0, 2);
        rs1 += __shfl_xor_sync(0xffffffffu, rs1, 1);
        rs1 += __shfl_xor_sync(0xffffffffu, rs1, 2);

        m0 = mn0; m1 = mn1;
        l0 = l0 * a0 + rs0;
        l1 = l1 * a1 + rs1;

#pragma unroll
        for (int nf = 0; nf < 8; nf++) {
            oacc[nf][0] *= a0; oacc[nf][1] *= a0;
            oacc[nf][2] *= a1; oacc[nf][3] *= a1;
        }

#pragma unroll
        for (int j = 0; j < 8; j++) {
            uint32_t pa[4];
            pa[0] = pack2h(sacc[2 * j][0], sacc[2 * j][1]);
            pa[1] = pack2h(sacc[2 * j][2], sacc[2 * j][3]);
            pa[2] = pack2h(sacc[2 * j + 1][0], sacc[2 * j + 1][1]);
            pa[3] = pack2h(sacc[2 * j + 1][2], sacc[2 * j + 1][3]);
            const int bc = j * 16 + bcsel;
#pragma unroll
            for (int nn = 0; nn < 8; nn += 2) {
                uint32_t t[4];
                LDSM4(t, sm_addr(&vP[(nn * 8 + br) * VSP + bc]));
                mma16816(oacc[nn], pa, t);
                mma16816(oacc[nn + 1], pa, t + 2);
            }
        }
        __syncthreads();
    }

    // ---- epilogue: O/l, store ctx fp16 ----
    const float il0 = 1.f / l0, il1 = 1.f / l1;
    const int mA = q0 + wid * 16 + gid;
    const int mB = mA + 8;
#pragma unroll
    for (int nf = 0; nf < 8; nf++) {
        const int col = h * 64 + nf * 8 + 2 * tig;
        *(uint32_t*)(ch_g + (size_t)mA * DM + col) =
            pack2h(oacc[nf][0] * il0, oacc[nf][1] * il0);
        *(uint32_t*)(ch_g + (size_t)mB * DM + col) =
            pack2h(oacc[nf][2] * il1, oacc[nf][3] * il1);
    }
}

// ---------------- transpose + convert weights: W[R,C] fp32 -> WT[C,R] fp16 ----------------
__global__ void trans_cvt_k(const float* __restrict__ in, h16* __restrict__ oh,
                            int R, int C, long long izs, long long ozs)
{
    __shared__ float t[32][33];
    in += (size_t)blockIdx.z * izs;
    oh += (size_t)blockIdx.z * ozs;
    const int r0 = blockIdx.y * 32, c0 = blockIdx.x * 32;
    const int tx = threadIdx.x, ty = threadIdx.y;
#pragma unroll
    for (int i = 0; i < 32; i += 8)
        t[ty + i][tx] = in[(size_t)(r0 + ty + i) * C + c0 + tx];
    __syncthreads();
#pragma unroll
    for (int i = 0; i < 32; i += 8)
        oh[(size_t)(c0 + ty + i) * R + r0 + tx] = __float2half_rn(t[tx][ty + i]);
}

// ---------------- bias concat: [bq|bk|bv] per layer ----------------
__global__ void concat_bias_k(const float* __restrict__ bq, const float* __restrict__ bk,
                              const float* __restrict__ bv, float* __restrict__ out)
{
    int l = blockIdx.x, w = blockIdx.y, i = threadIdx.x;
    const float* s = (w == 0) ? bq : ((w == 1) ? bk : bv);
    out[(size_t)(l * 3 + w) * DM + i] = s[(size_t)l * DM + i];
}

// ---------------- strided fp16 transpose: a[R,C] (lda) -> at[C,R] (ldat) ----------------
__global__ void trans_h_k(const h16* __restrict__ a, h16* __restrict__ at,
                          int lda, int ldat)
{
    __shared__ h16 ta[32][33];
    const int r0 = blockIdx.y * 32, c0 = blockIdx.x * 32;
    const int tx = threadIdx.x, ty = threadIdx.y;
#pragma unroll
    for (int i = 0; i < 32; i += 8)
        ta[ty + i][tx] = a[(size_t)(r0 + ty + i) * lda + c0 + tx];
    __syncthreads();
#pragma unroll
    for (int i = 0; i < 32; i += 8)
        at[(size_t)(c0 + ty + i) * ldat + r0 + tx] = ta[tx][ty + i];
}

// ---------------- elementwise fp32 -> fp16 ----------------
__global__ void cvt_h_k(const float* __restrict__ x, h16* __restrict__ h, int n)
{
    int i = blockIdx.x * 256 + threadIdx.x;
    if (i < n) h[i] = __float2half_rn(x[i]);
}

// ---------------- residual + LayerNorm, writes x fp32 and fp16 ----------------
__global__ __launch_bounds__(256) void add_ln_k(
    float* __restrict__ x, const float* __restrict__ y,
    const float* __restrict__ g, const float* __restrict__ b,
    h16* __restrict__ xh)
{
    __shared__ float r[DM];
    __shared__ float red[256];
    const int tid = threadIdx.x;
    const size_t off = (size_t)blockIdx.x * DM;

    float lsum = 0.f;
    for (int j = tid; j < DM; j += 256) {
        float v = x[off + j] + y[off + j];
        r[j] = v;
        lsum += v;
    }
    red[tid] = lsum; __syncthreads();
    for (int st = 128; st > 0; st >>= 1) {
        if (tid < st) red[tid] += red[tid + st];
        __syncthreads();
    }
    const float mu = red[0] * (1.0f / DM);
    __syncthreads();

    float lv = 0.f;
    for (int j = tid; j < DM; j += 256) {
        float d = r[j] - mu;
        lv += d * d;
    }
    red[tid] = lv; __syncthreads();
    for (int st = 128; st > 0; st >>= 1) {
        if (tid < st) red[tid] += red[tid + st];
        __syncthreads();
    }
    const float rstd = rsqrtf(red[0] * (1.0f / DM) + 1e-5f);

    for (int j = tid; j < DM; j += 256) {
        float v = (r[j] - mu) * rstd * g[j] + b[j];
        x[off + j] = v;
        xh[off + j] = __float2half_rn(v);
    }
}

// ---------------- host launch ----------------
static const int SMEM128 = (2 * 128 * 40 + 2 * 128 * 40) * 2;    // 40960
static const int SMEM64  = (2 * 64 * 40 + 2 * 128 * 40) * 2;     // 30720
static const int SMEMFA  = (2 * 128 * 72 + 2 * 64 * 136) * 2;    // 71680

extern "C" void kernel_launch(void* const* d_in, const int* in_sizes, int n_in,
                              void* d_out, int out_size)
{
    const float* x_in = (const float*)d_in[0];
    const float* wq = (const float*)d_in[1];
    const float* bq = (const float*)d_in[2];
    const float* wk = (const float*)d_in[3];
    const float* bk = (const float*)d_in[4];
    const float* wv = (const float*)d_in[5];
    const float* bv = (const float*)d_in[6];
    const float* wo = (const float*)d_in[7];
    const float* bo = (const float*)d_in[8];
    const float* w1 = (const float*)d_in[9];
    const float* b1 = (const float*)d_in[10];
    const float* w2 = (const float*)d_in[11];
    const float* b2 = (const float*)d_in[12];
    const float* ln1g = (const float*)d_in[13];
    const float* ln1b = (const float*)d_in[14];
    const float* ln2g = (const float*)d_in[15];
    const float* ln2b = (const float*)d_in[16];

    float* x = (float*)d_out;

    h16 *wqkvT, *woT, *w1T, *w2T;
    h16 *xh, *qkv, *vth, *ch, *hh;
    float *tmp, *bqkv;
    cudaGetSymbolAddress((void**)&wqkvT, g_wqkvT);
    cudaGetSymbolAddress((void**)&bqkv, g_bqkv);
    cudaGetSymbolAddress((void**)&woT, g_woT);
    cudaGetSymbolAddress((void**)&w1T, g_w1T);
    cudaGetSymbolAddress((void**)&w2T, g_w2T);
    cudaGetSymbolAddress((void**)&xh, g_xh);
    cudaGetSymbolAddress((void**)&qkv, g_qkv);
    cudaGetSymbolAddress((void**)&vth, g_vth);
    cudaGetSymbolAddress((void**)&ch, g_ch);
    cudaGetSymbolAddress((void**)&hh, g_hh);
    cudaGetSymbolAddress((void**)&tmp, g_tmp);

    cudaFuncSetAttribute(mmsync<3, 128>, cudaFuncAttributeMaxDynamicSharedMemorySize, SMEM128);
    cudaFuncSetAttribute(mmsync<4, 128>, cudaFuncAttributeMaxDynamicSharedMemorySize, SMEM128);
    cudaFuncSetAttribute(mmsync<1, 64>,  cudaFuncAttributeMaxDynamicSharedMemorySize, SMEM64);
    cudaFuncSetAttribute(flash_attn, cudaFuncAttributeMaxDynamicSharedMemorySize, SMEMFA);

    const dim3 tb(32, 8);
    const long long WZ = (long long)DM * DM;
    const long long QZ = 3LL * DM * DM;
    trans_cvt_k<<<dim3(DM / 32, DM / 32, NL), tb>>>(wq, wqkvT, DM, DM, WZ, QZ);
    trans_cvt_k<<<dim3(DM / 32, DM / 32, NL), tb>>>(wk, wqkvT + (size_t)DM * DM, DM, DM, WZ, QZ);
    trans_cvt_k<<<dim3(DM / 32, DM / 32, NL), tb>>>(wv, wqkvT + 2 * (size_t)DM * DM, DM, DM, WZ, QZ);
    trans_cvt_k<<<dim3(DM / 32, DM / 32, NL), tb>>>(wo, woT, DM, DM, WZ, WZ);
    trans_cvt_k<<<dim3(DFF / 32, DM / 32, NL), tb>>>(w1, w1T, DM, DFF,
        (long long)DM * DFF, (long long)DM * DFF);
    trans_cvt_k<<<dim3(DM / 32, DFF / 32, NL), tb>>>(w2, w2T, DFF, DM,
        (long long)DM * DFF, (long long)DM * DFF);
    concat_bias_k<<<dim3(NL, 3), DM>>>(bq, bk, bv, bqkv);

    cudaMemcpyAsync(x, x_in, (size_t)SEQ * DM * sizeof(float), cudaMemcpyDeviceToDevice);
    cvt_h_k<<<(SEQ * DM) / 256, 256>>>(x_in, xh, SEQ * DM);

    const dim3 gQKV(3 * DM / 128, SEQ / 128);  // (24,16) = 384 CTAs, MT=128
    const dim3 gP64(DM / 128, SEQ / 64);       // (8,32)  = 256 CTAs, MT=64
    const dim3 gFA(NH, SEQ / 128);             // (16,16)
    const dim3 gF1(DFF / 128, SEQ / 128);      // (32,16) = 512 CTAs, MT=128

    for (int l = 0; l < NL; l++) {
        const size_t lW = (size_t)l * DM * DM;
        const size_t lQ = (size_t)l * 3 * DM * DM;
        const size_t lF = (size_t)l * DM * DFF;

        // fused q|k|v projection (MT=128, as in R14)
        mmsync<3, 128><<<gQKV, 256, SMEM128>>>(xh, wqkvT + lQ, bqkv + (size_t)l * 3 * DM,
            nullptr, qkv, DM, DM, DM, LDQKV);
        // V^T from qkv's v slice (stride LDQKV)
        trans_h_k<<<dim3(DM / 32, SEQ / 32), tb>>>(qkv + 2 * DM, vth, LDQKV, SEQ);

        // fused attention: scores + softmax + AV
        flash_attn<<<gFA, 256, SMEMFA>>>(qkv, vth, ch);

        // attn_out = ctx @ Wo + bo (MT=64 -> 256 CTAs, full wave)
        mmsync<1, 64><<<gP64, 256, SMEM64>>>(ch, woT + lW, bo + l * DM,
            tmp, nullptr, DM, DM, DM, DM);

        add_ln_k<<<SEQ, 256>>>(x, tmp, ln1g + l * DM, ln1b + l * DM, xh);

        // h = gelu(x @ W1 + b1) (MT=128, as in R14)
        mmsync<4, 128><<<gF1, 256, SMEM128>>>(xh, w1T + lF, b1 + l * DFF,
            nullptr, hh, DM, DM, DM, DFF);

        // ffn_out = h @ W2 + b2 (MT=64 -> 256 CTAs, full wave)
        mmsync<1, 64><<<gP64, 256, SMEM64>>>(hh, w2T + lF, b2 + l * DM,
            tmp, nullptr, DFF, DFF, DFF, DM);

        add_ln_k<<<SEQ, 256>>>(x, tmp, ln2g + l * DM, ln2b + l * DM, xh);
    }
}

// round 17
// speedup vs baseline: 1.0810x; 1.0382x over previous
#include <cuda_runtime.h>
#include <cuda_fp16.h>
#include <math.h>
#include <stdint.h>

#define SEQ 2048
#define DM  1024
#define NH  16
#define DK  64
#define DFF 4096
#define NL  4
#define LDQKV (3 * DM)

typedef __half h16;

// ---------------- device scratch (no cudaMalloc allowed) ----------------
__device__ h16 g_wqkvT[NL * 3 * DM * DM];     // [3*DM rows, DM cols] per layer
__device__ float g_bqkv[NL * 3 * DM];
__device__ h16 g_woT[NL * DM * DM];
__device__ h16 g_w1T[NL * DM * DFF];
__device__ h16 g_w2T[NL * DM * DFF];
__device__ h16 g_xh[SEQ * DM];
__device__ h16 g_qkv[SEQ * 3 * DM];           // fused q|k|v
__device__ h16 g_ch[SEQ * DM];
__device__ h16 g_hh[SEQ * DFF];
__device__ float g_tmp[SEQ * DM];

// ---------------- small helpers ----------------
__device__ __forceinline__ float tanh_fast(float y) {
    return 1.0f - 2.0f / (__expf(2.0f * y) + 1.0f);
}
__device__ __forceinline__ float gelu_f(float v) {
    return 0.5f * v * (1.0f + tanh_fast(0.7978845608028654f *
                                        (v + 0.044715f * v * v * v)));
}
__device__ __forceinline__ uint32_t pack2h(float x, float y) {
    __half2 p = __floats2half2_rn(x, y);
    return *(uint32_t*)&p;
}
__device__ __forceinline__ void cpa16(uint32_t dst, const void* src) {
    asm volatile("cp.async.cg.shared.global [%0], [%1], 16;" :: "r"(dst), "l"(src));
}
#define CP_COMMIT() asm volatile("cp.async.commit_group;" ::: "memory")
#define CP_WAIT0()  asm volatile("cp.async.wait_group 0;" ::: "memory")
#define CP_WAIT1()  asm volatile("cp.async.wait_group 1;" ::: "memory")
#define LDSM4(r, a) asm volatile( \
    "ldmatrix.sync.aligned.m8n8.x4.shared.b16 {%0,%1,%2,%3}, [%4];" \
    : "=r"((r)[0]), "=r"((r)[1]), "=r"((r)[2]), "=r"((r)[3]) : "r"(a))
#define LDSM4T(r, a) asm volatile( \
    "ldmatrix.sync.aligned.m8n8.x4.trans.shared.b16 {%0,%1,%2,%3}, [%4];" \
    : "=r"((r)[0]), "=r"((r)[1]), "=r"((r)[2]), "=r"((r)[3]) : "r"(a))

__device__ __forceinline__ void mma16816(float* c, const uint32_t* a, const uint32_t* b) {
    asm volatile(
        "mma.sync.aligned.m16n8k16.row.col.f32.f16.f16.f32 "
        "{%0,%1,%2,%3}, {%4,%5,%6,%7}, {%8,%9}, {%0,%1,%2,%3};"
        : "+f"(c[0]), "+f"(c[1]), "+f"(c[2]), "+f"(c[3])
        : "r"(a[0]), "r"(a[1]), "r"(a[2]), "r"(a[3]), "r"(b[0]), "r"(b[1]));
}
__device__ __forceinline__ uint32_t sm_addr(const void* p) {
    return (uint32_t)__cvta_generic_to_shared(p);
}

// ---------------- mma.sync GEMM: 128x128 tile, pure fp16, 2 CTA/SM ----------------
// C = A @ B^T [+bias][gelu]
// EPI: 1 f32+bias, 3 fp16+bias, 4 gelu fp16+bias
template <int EPI>
__global__ __launch_bounds__(256, 2) void mmsync(
    const h16* __restrict__ Ah, const h16* __restrict__ Bh,
    const float* __restrict__ bias,
    float* __restrict__ Cf, h16* __restrict__ Ch,
    int K, int lda, int ldb, int ldc)
{
    constexpr int SP  = 40;
    constexpr int AST = 128 * SP;
    constexpr int MF  = 4;
    constexpr int NF  = 4;

    extern __shared__ h16 sm[];
    h16* sA = sm;                          // 2 * AST
    h16* sB = sA + 2 * AST;                // 2 * AST

    const int tid = threadIdx.x;
    const int wid = tid >> 5;
    const int lane = tid & 31;
    const int gid = lane >> 2, tig = lane & 3;
    const int bm = blockIdx.y * 128;
    const int bn = blockIdx.x * 128;

    const int wm0 = (wid >> 2) * 64;
    const int wn0 = (wid & 3) * 32;

    float acc[MF][NF][4];
#pragma unroll
    for (int i = 0; i < MF; i++)
#pragma unroll
        for (int j = 0; j < NF; j++)
#pragma unroll
            for (int q = 0; q < 4; q++) acc[i][j][q] = 0.f;

    const int nk = K >> 5;

    auto loadStage = [&](int st, int k0) {
#pragma unroll
        for (int i = 0; i < 2; i++) {
            int ch = tid + i * 256;
            int row = ch >> 2, c = ch & 3;
            size_t ga = (size_t)(bm + row) * lda + k0 + c * 8;
            size_t gb = (size_t)(bn + row) * ldb + k0 + c * 8;
            int so = st * AST + row * SP + c * 8;
            cpa16(sm_addr(&sA[so]), Ah + ga);
            cpa16(sm_addr(&sB[so]), Bh + gb);
        }
    };

    loadStage(0, 0);
    CP_COMMIT();

    const int ar = lane & 15;
    const int acb = (lane >> 4) << 3;
    const int br = (lane < 16) ? (lane & 7) : 8 + (lane & 7);
    const int bcsel = ((lane >> 3) & 1) << 3;

    for (int kt = 0; kt < nk; kt++) {
        if (kt + 1 < nk) {
            loadStage((kt + 1) & 1, (kt + 1) << 5);
            CP_COMMIT();
            CP_WAIT1();
        } else {
            CP_WAIT0();
        }
        __syncthreads();

        const int st = kt & 1;
        const h16* aP = sA + st * AST;
        const h16* bP = sB + st * AST;

#pragma unroll
        for (int kk = 0; kk < 2; kk++) {
            const int koff = kk * 16;
            uint32_t af[MF][4];
#pragma unroll
            for (int mf = 0; mf < MF; mf++) {
                int r = wm0 + mf * 16 + ar;
                LDSM4(af[mf], sm_addr(&aP[r * SP + koff + acb]));
            }
            uint32_t bf[NF][2];
            const int bc = koff + bcsel;
#pragma unroll
            for (int nn = 0; nn < NF; nn += 2) {
                int r = wn0 + nn * 8 + br;
                uint32_t t[4];
                LDSM4(t, sm_addr(&bP[r * SP + bc]));
                bf[nn][0] = t[0]; bf[nn][1] = t[1];
                bf[nn + 1][0] = t[2]; bf[nn + 1][1] = t[3];
            }
#pragma unroll
            for (int mf = 0; mf < MF; mf++)
#pragma unroll
                for (int nf = 0; nf < NF; nf++)
                    mma16816(acc[mf][nf], af[mf], bf[nf]);
        }
        __syncthreads();
    }

    // ---------------- epilogue ----------------
#pragma unroll
    for (int mf = 0; mf < MF; mf++) {
        const int mA = bm + wm0 + mf * 16 + gid;
        const int mB = mA + 8;
#pragma unroll
        for (int nf = 0; nf < NF; nf++) {
            const int n = bn + wn0 + nf * 8 + 2 * tig;
            float b0 = bias[n], b1 = bias[n + 1];
            float v0 = acc[mf][nf][0] + b0, v1 = acc[mf][nf][1] + b1;
            float v2 = acc[mf][nf][2] + b0, v3 = acc[mf][nf][3] + b1;
            if (EPI == 1) {
                *(float2*)(Cf + (size_t)mA * ldc + n) = make_float2(v0, v1);
                *(float2*)(Cf + (size_t)mB * ldc + n) = make_float2(v2, v3);
            } else {
                if (EPI == 4) {
                    v0 = gelu_f(v0); v1 = gelu_f(v1);
                    v2 = gelu_f(v2); v3 = gelu_f(v3);
                }
                *(uint32_t*)(Ch + (size_t)mA * ldc + n) = pack2h(v0, v1);
                *(uint32_t*)(Ch + (size_t)mB * ldc + n) = pack2h(v2, v3);
            }
        }
    }
}

// ---------------- flash attention: S=QK^T/8, online softmax, O=PV ----------------
// grid (NH, SEQ/128), 256 threads. Q/K/V all read from fused qkv (stride LDQKV).
// V loaded in natural [s, d] layout; PV uses ldmatrix.trans for B fragments.
__global__ __launch_bounds__(256) void flash_attn(
    const h16* __restrict__ qkv_g,      // q at +0, k at +DM, v at +2*DM
    h16* __restrict__ ch_g)
{
    constexpr int KSP = 72;
    constexpr int KST = 128 * KSP;      // K tile and V tile share this shape
    const int h = blockIdx.x;
    const int q0 = blockIdx.y * 128;
    const int tid = threadIdx.x, wid = tid >> 5, lane = tid & 31;
    const int gid = lane >> 2, tig = lane & 3;

    const h16* qh_g = qkv_g;
    const h16* kh_g = qkv_g + DM;
    const h16* vh_g = qkv_g + 2 * DM;

    extern __shared__ h16 sm[];
    h16* sK = sm;                          // 2 * KST
    h16* sV = sK + 2 * KST;                // 2 * KST

    // ---- prologue: Q tile into stage-0 K buffer, extract frags ----
#pragma unroll
    for (int i = 0; i < 4; i++) {
        int ch = tid + i * 256;
        int row = ch >> 3, c = ch & 7;
        size_t g = (size_t)(q0 + row) * LDQKV + h * 64 + c * 8;
        cpa16(sm_addr(&sK[row * KSP + c * 8]), qh_g + g);
    }
    CP_COMMIT(); CP_WAIT0();
    __syncthreads();

    uint32_t qf[4][4];
    {
        const int ar = lane & 15, acb = (lane >> 4) << 3;
#pragma unroll
        for (int kf = 0; kf < 4; kf++) {
            int off = (wid * 16 + ar) * KSP + kf * 16 + acb;
            LDSM4(qf[kf], sm_addr(&sK[off]));
        }
    }
    __syncthreads();

    float oacc[8][4];
#pragma unroll
    for (int i = 0; i < 8; i++)
#pragma unroll
        for (int q = 0; q < 4; q++) oacc[i][q] = 0.f;
    float m0 = -1e30f, m1 = -1e30f, l0 = 0.f, l1 = 0.f;

    auto loadKV = [&](int st, int s0) {
        // K and V tiles: each 128 rows x 64 halfs = 1024 chunks of 8
#pragma unroll
        for (int i = 0; i < 4; i++) {
            int ch = tid + i * 256;
            int row = ch >> 3, c = ch & 7;
            size_t g = (size_t)(s0 + row) * LDQKV + h * 64 + c * 8;
            int so = st * KST + row * KSP + c * 8;
            cpa16(sm_addr(&sK[so]), kh_g + g);
            cpa16(sm_addr(&sV[so]), vh_g + g);
        }
    };

    loadKV(0, 0);
    CP_COMMIT();

    const int br = (lane < 16) ? (lane & 7) : 8 + (lane & 7);
    const int bcsel = ((lane >> 3) & 1) << 3;
    // V trans-load lane mapping: group g = lane>>3 -> (k-half g&1, n-tile g>>1)
    const int vs = ((lane >> 3) & 1) * 8 + (lane & 7);  // s-row within 16-chunk
    const int vd = (lane >> 4) << 3;                     // d offset 0 or 8

    for (int kt = 0; kt < SEQ / 128; kt++) {
        if (kt + 1 < SEQ / 128) {
            loadKV((kt + 1) & 1, (kt + 1) * 128);
            CP_COMMIT();
            CP_WAIT1();
        } else {
            CP_WAIT0();
        }
        __syncthreads();

        const int st = kt & 1;
        const h16* kP = sK + st * KST;
        const h16* vP = sV + st * KST;

        float sacc[16][4];
#pragma unroll
        for (int i = 0; i < 16; i++)
#pragma unroll
            for (int q = 0; q < 4; q++) sacc[i][q] = 0.f;

#pragma unroll
        for (int kf = 0; kf < 4; kf++) {
            const int bc = kf * 16 + bcsel;
#pragma unroll
            for (int nn = 0; nn < 16; nn += 2) {
                uint32_t t[4];
                LDSM4(t, sm_addr(&kP[(nn * 8 + br) * KSP + bc]));
                mma16816(sacc[nn], qf[kf], t);
                mma16816(sacc[nn + 1], qf[kf], t + 2);
            }
        }

        float tm0 = -1e30f, tm1 = -1e30f;
#pragma unroll
        for (int nf = 0; nf < 16; nf++) {
            sacc[nf][0] *= 0.125f; sacc[nf][1] *= 0.125f;
            sacc[nf][2] *= 0.125f; sacc[nf][3] *= 0.125f;
            tm0 = fmaxf(tm0, fmaxf(sacc[nf][0], sacc[nf][1]));
            tm1 = fmaxf(tm1, fmaxf(sacc[nf][2], sacc[nf][3]));
        }
        tm0 = fmaxf(tm0, __shfl_xor_sync(0xffffffffu, tm0, 1));
        tm0 = fmaxf(tm0, __shfl_xor_sync(0xffffffffu, tm0, 2));
        tm1 = fmaxf(tm1, __shfl_xor_sync(0xffffffffu, tm1, 1));
        tm1 = fmaxf(tm1, __shfl_xor_sync(0xffffffffu, tm1, 2));

        const float mn0 = fmaxf(m0, tm0), mn1 = fmaxf(m1, tm1);
        const float a0 = __expf(m0 - mn0), a1 = __expf(m1 - mn1);

        float rs0 = 0.f, rs1 = 0.f;
#pragma unroll
        for (int nf = 0; nf < 16; nf++) {
            sacc[nf][0] = __expf(sacc[nf][0] - mn0);
            sacc[nf][1] = __expf(sacc[nf][1] - mn0);
            sacc[nf][2] = __expf(sacc[nf][2] - mn1);
            sacc[nf][3] = __expf(sacc[nf][3] - mn1);
            rs0 += sacc[nf][0] + sacc[nf][1];
            rs1 += sacc[nf][2] + sacc[nf][3];
        }
        rs0 += __shfl_xor_sync(0xffffffffu, rs0, 1);
        rs0 += __shfl_xor_sync(0xffffffffu, rs0, 2);
        rs1 += __shfl_xor_sync(0xffffffffu, rs1, 1);
        rs1 += __shfl_xor_sync(0xffffffffu, rs1, 2);

        m0 = mn0; m1 = mn1;
        l0 = l0 * a0 + rs0;
        l1 = l1 * a1 + rs1;

#pragma unroll
        for (int nf = 0; nf < 8; nf++) {
            oacc[nf][0] *= a0; oacc[nf][1] *= a0;
            oacc[nf][2] *= a1; oacc[nf][3] *= a1;
        }

        // O += P @ V  (V in [s, d] layout, trans-loaded as B fragments)
#pragma unroll
        for (int j = 0; j < 8; j++) {
            uint32_t pa[4];
            pa[0] = pack2h(sacc[2 * j][0], sacc[2 * j][1]);
            pa[1] = pack2h(sacc[2 * j][2], sacc[2 * j][3]);
            pa[2] = pack2h(sacc[2 * j + 1][0], sacc[2 * j + 1][1]);
            pa[3] = pack2h(sacc[2 * j + 1][2], sacc[2 * j + 1][3]);
            const int srow = j * 16 + vs;
#pragma unroll
            for (int nn = 0; nn < 8; nn += 2) {
                uint32_t t[4];
                LDSM4T(t, sm_addr(&vP[srow * KSP + nn * 8 + vd]));
                mma16816(oacc[nn], pa, t);
                mma16816(oacc[nn + 1], pa, t + 2);
            }
        }
        __syncthreads();
    }

    // ---- epilogue: O/l, store ctx fp16 ----
    const float il0 = 1.f / l0, il1 = 1.f / l1;
    const int mA = q0 + wid * 16 + gid;
    const int mB = mA + 8;
#pragma unroll
    for (int nf = 0; nf < 8; nf++) {
        const int col = h * 64 + nf * 8 + 2 * tig;
        *(uint32_t*)(ch_g + (size_t)mA * DM + col) =
            pack2h(oacc[nf][0] * il0, oacc[nf][1] * il0);
        *(uint32_t*)(ch_g + (size_t)mB * DM + col) =
            pack2h(oacc[nf][2] * il1, oacc[nf][3] * il1);
    }
}

// ---------------- transpose + convert weights: W[R,C] fp32 -> WT[C,R] fp16 ----------------
__global__ void trans_cvt_k(const float* __restrict__ in, h16* __restrict__ oh,
                            int R, int C, long long izs, long long ozs)
{
    __shared__ float t[32][33];
    in += (size_t)blockIdx.z * izs;
    oh += (size_t)blockIdx.z * ozs;
    const int r0 = blockIdx.y * 32, c0 = blockIdx.x * 32;
    const int tx = threadIdx.x, ty = threadIdx.y;
#pragma unroll
    for (int i = 0; i < 32; i += 8)
        t[ty + i][tx] = in[(size_t)(r0 + ty + i) * C + c0 + tx];
    __syncthreads();
#pragma unroll
    for (int i = 0; i < 32; i += 8)
        oh[(size_t)(c0 + ty + i) * R + r0 + tx] = __float2half_rn(t[tx][ty + i]);
}

// ---------------- bias concat: [bq|bk|bv] per layer ----------------
__global__ void concat_bias_k(const float* __restrict__ bq, const float* __restrict__ bk,
                              const float* __restrict__ bv, float* __restrict__ out)
{
    int l = blockIdx.x, w = blockIdx.y, i = threadIdx.x;
    const float* s = (w == 0) ? bq : ((w == 1) ? bk : bv);
    out[(size_t)(l * 3 + w) * DM + i] = s[(size_t)l * DM + i];
}

// ---------------- elementwise fp32 -> fp16 ----------------
__global__ void cvt_h_k(const float* __restrict__ x, h16* __restrict__ h, int n)
{
    int i = blockIdx.x * 256 + threadIdx.x;
    if (i < n) h[i] = __float2half_rn(x[i]);
}

// ---------------- residual + LayerNorm, writes x fp32 and fp16 ----------------
__global__ __launch_bounds__(256) void add_ln_k(
    float* __restrict__ x, const float* __restrict__ y,
    const float* __restrict__ g, const float* __restrict__ b,
    h16* __restrict__ xh)
{
    __shared__ float r[DM];
    __shared__ float red[256];
    const int tid = threadIdx.x;
    const size_t off = (size_t)blockIdx.x * DM;

    float lsum = 0.f;
    for (int j = tid; j < DM; j += 256) {
        float v = x[off + j] + y[off + j];
        r[j] = v;
        lsum += v;
    }
    red[tid] = lsum; __syncthreads();
    for (int st = 128; st > 0; st >>= 1) {
        if (tid < st) red[tid] += red[tid + st];
        __syncthreads();
    }
    const float mu = red[0] * (1.0f / DM);
    __syncthreads();

    float lv = 0.f;
    for (int j = tid; j < DM; j += 256) {
        float d = r[j] - mu;
        lv += d * d;
    }
    red[tid] = lv; __syncthreads();
    for (int st = 128; st > 0; st >>= 1) {
        if (tid < st) red[tid] += red[tid + st];
        __syncthreads();
    }
    const float rstd = rsqrtf(red[0] * (1.0f / DM) + 1e-5f);

    for (int j = tid; j < DM; j += 256) {
        float v = (r[j] - mu) * rstd * g[j] + b[j];
        x[off + j] = v;
        xh[off + j] = __float2half_rn(v);
    }
}

// ---------------- host launch ----------------
static const int SMEMMM = 2 * 2 * 128 * 40 * 2;      // 40960
static const int SMEMFA = 4 * 128 * 72 * 2;          // 73728 (2 stages x K,V tiles)

extern "C" void kernel_launch(void* const* d_in, const int* in_sizes, int n_in,
                              void* d_out, int out_size)
{
    const float* x_in = (const float*)d_in[0];
    const float* wq = (const float*)d_in[1];
    const float* bq = (const float*)d_in[2];
    const float* wk = (const float*)d_in[3];
    const float* bk = (const float*)d_in[4];
    const float* wv = (const float*)d_in[5];
    const float* bv = (const float*)d_in[6];
    const float* wo = (const float*)d_in[7];
    const float* bo = (const float*)d_in[8];
    const float* w1 = (const float*)d_in[9];
    const float* b1 = (const float*)d_in[10];
    const float* w2 = (const float*)d_in[11];
    const float* b2 = (const float*)d_in[12];
    const float* ln1g = (const float*)d_in[13];
    const float* ln1b = (const float*)d_in[14];
    const float* ln2g = (const float*)d_in[15];
    const float* ln2b = (const float*)d_in[16];

    float* x = (float*)d_out;

    h16 *wqkvT, *woT, *w1T, *w2T;
    h16 *xh, *qkv, *ch, *hh;
    float *tmp, *bqkv;
    cudaGetSymbolAddress((void**)&wqkvT, g_wqkvT);
    cudaGetSymbolAddress((void**)&bqkv, g_bqkv);
    cudaGetSymbolAddress((void**)&woT, g_woT);
    cudaGetSymbolAddress((void**)&w1T, g_w1T);
    cudaGetSymbolAddress((void**)&w2T, g_w2T);
    cudaGetSymbolAddress((void**)&xh, g_xh);
    cudaGetSymbolAddress((void**)&qkv, g_qkv);
    cudaGetSymbolAddress((void**)&ch, g_ch);
    cudaGetSymbolAddress((void**)&hh, g_hh);
    cudaGetSymbolAddress((void**)&tmp, g_tmp);

    cudaFuncSetAttribute(mmsync<1>, cudaFuncAttributeMaxDynamicSharedMemorySize, SMEMMM);
    cudaFuncSetAttribute(mmsync<3>, cudaFuncAttributeMaxDynamicSharedMemorySize, SMEMMM);
    cudaFuncSetAttribute(mmsync<4>, cudaFuncAttributeMaxDynamicSharedMemorySize, SMEMMM);
    cudaFuncSetAttribute(flash_attn, cudaFuncAttributeMaxDynamicSharedMemorySize, SMEMFA);

    const dim3 tb(32, 8);
    const long long WZ = (long long)DM * DM;
    const long long QZ = 3LL * DM * DM;
    trans_cvt_k<<<dim3(DM / 32, DM / 32, NL), tb>>>(wq, wqkvT, DM, DM, WZ, QZ);
    trans_cvt_k<<<dim3(DM / 32, DM / 32, NL), tb>>>(wk, wqkvT + (size_t)DM * DM, DM, DM, WZ, QZ);
    trans_cvt_k<<<dim3(DM / 32, DM / 32, NL), tb>>>(wv, wqkvT + 2 * (size_t)DM * DM, DM, DM, WZ, QZ);
    trans_cvt_k<<<dim3(DM / 32, DM / 32, NL), tb>>>(wo, woT, DM, DM, WZ, WZ);
    trans_cvt_k<<<dim3(DFF / 32, DM / 32, NL), tb>>>(w1, w1T, DM, DFF,
        (long long)DM * DFF, (long long)DM * DFF);
    trans_cvt_k<<<dim3(DM / 32, DFF / 32, NL), tb>>>(w2, w2T, DFF, DM,
        (long long)DM * DFF, (long long)DM * DFF);
    concat_bias_k<<<dim3(NL, 3), DM>>>(bq, bk, bv, bqkv);

    cudaMemcpyAsync(x, x_in, (size_t)SEQ * DM * sizeof(float), cudaMemcpyDeviceToDevice);
    cvt_h_k<<<(SEQ * DM) / 256, 256>>>(x_in, xh, SEQ * DM);

    const dim3 gQKV(3 * DM / 128, SEQ / 128);  // (24,16)
    const dim3 gP(DM / 128, SEQ / 128);        // (8,16)
    const dim3 gFA(NH, SEQ / 128);             // (16,16)
    const dim3 gF1(DFF / 128, SEQ / 128);      // (32,16)

    for (int l = 0; l < NL; l++) {
        const size_t lW = (size_t)l * DM * DM;
        const size_t lQ = (size_t)l * 3 * DM * DM;
        const size_t lF = (size_t)l * DM * DFF;

        // fused q|k|v projection
        mmsync<3><<<gQKV, 256, SMEMMM>>>(xh, wqkvT + lQ, bqkv + (size_t)l * 3 * DM,
            nullptr, qkv, DM, DM, DM, LDQKV);

        // fused attention: scores + softmax + AV (V read directly, no transpose)
        flash_attn<<<gFA, 256, SMEMFA>>>(qkv, ch);

        mmsync<1><<<gP, 256, SMEMMM>>>(ch, woT + lW, bo + l * DM,
            tmp, nullptr, DM, DM, DM, DM);

        add_ln_k<<<SEQ, 256>>>(x, tmp, ln1g + l * DM, ln1b + l * DM, xh);

        mmsync<4><<<gF1, 256, SMEMMM>>>(xh, w1T + lF, b1 + l * DFF,
            nullptr, hh, DM, DM, DM, DFF);

        mmsync<1><<<gP, 256, SMEMMM>>>(hh, w2T + lF, b2 + l * DM,
            tmp, nullptr, DFF, DFF, DFF, DM);

        add_ln_k<<<SEQ, 256>>>(x, tmp, ln2g + l * DM, ln2b + l * DM, xh);
    }
}